// round 2
// baseline (speedup 1.0000x reference)
#include <cuda_runtime.h>
#include <math.h>

#define BB 4
#define TT 64
#define FF 64
#define UU 64
#define MM 64
#define TF 4096   // T*F

// Scratch (device globals: no allocation allowed)
__device__ float g_h[BB * TT * UU];
__device__ float g_out[BB * TT * FF];
__device__ float g_score[BB * TT * FF];

// ---------------------------------------------------------------------------
// K_A: one block per (b,t), 64 threads.
//   h[u]     = tanh(inputs[b,t,:] @ Wk[:,u] + bk[u])
//   out[f]   = h @ Wv[:,f] + bv[f]            (also final "output" tensor)
//   score[f] = sum_u tanh(h[u] * out[f] * w_s[63])
// ---------------------------------------------------------------------------
__global__ void __launch_bounds__(64) kA(
    const float* __restrict__ inputs, const float* __restrict__ Wk,
    const float* __restrict__ bk,     const float* __restrict__ Wv,
    const float* __restrict__ bv,     const float* __restrict__ ws,
    float* __restrict__ out_final)
{
    int bt  = blockIdx.x;      // b*64 + t
    int tid = threadIdx.x;     // 0..63

    __shared__ float s_in[FF];
    __shared__ float s_h[UU];

    s_in[tid] = inputs[bt * FF + tid];
    __syncthreads();

    // h[u], u = tid
    float acc = bk[tid];
#pragma unroll 16
    for (int f = 0; f < FF; f++)
        acc = fmaf(s_in[f], Wk[f * UU + tid], acc);
    float hv = tanhf(acc);
    s_h[tid] = hv;
    g_h[bt * UU + tid] = hv;
    __syncthreads();

    // out[f], f = tid
    float acc2 = bv[tid];
#pragma unroll 16
    for (int u = 0; u < UU; u++)
        acc2 = fmaf(s_h[u], Wv[u * FF + tid], acc2);
    g_out[bt * FF + tid]     = acc2;
    out_final[bt * FF + tid] = acc2;

    // score[f]
    float c  = acc2 * ws[63];
    float sc = 0.f;
#pragma unroll 8
    for (int u = 0; u < UU; u++)
        sc += tanhf(s_h[u] * c);
    g_score[bt * FF + tid] = sc;
}

// ---------------------------------------------------------------------------
// K_B: one block per batch, 256 threads. Argmax paths, set extremes,
// flat = tanh(extreme arg), logits GEMV, softmax, targets, importance, dist.
// ---------------------------------------------------------------------------
__global__ void __launch_bounds__(256) kB(
    const float* __restrict__ inputs, const float* __restrict__ ws,
    const float* __restrict__ mem_keys, const float* __restrict__ mem_vals,
    float* __restrict__ d_dist, float* __restrict__ d_imp)
{
    int b   = blockIdx.x;
    int tid = threadIdx.x;

    __shared__ float s_score[TF];           // 16 KB
    __shared__ float s_flat[TF];            // 16 KB
    __shared__ int   s_idxt[TT], s_idxf[FF];
    __shared__ int   s_usel[UU], s_ssel[TT];
    __shared__ float s_hmax[TT], s_hmin[TT];
    __shared__ float s_logit[MM], s_attn[MM];
    __shared__ float s_tgt[FF];
    __shared__ float s_q[2];                // qmax, qmin
    __shared__ float s_red[3];              // maxlogit, invsum, importance

    // Load this batch's score matrix
    {
        const float4* gs4 = (const float4*)(g_score + b * TF);
        float4* ss4 = (float4*)s_score;
        for (int i = tid; i < TF / 4; i += 256) ss4[i] = gs4[i];
    }
    if (tid < 64) { s_usel[tid] = 0; s_ssel[tid] = 0; }
    __syncthreads();

    // idx_f[f] = argmax_t score[t,f] (first max); idx_t[t] = argmax_f score[t,f]
    if (tid < 64) {
        int f = tid;
        float best = s_score[f]; int bi = 0;
        for (int t = 1; t < TT; t++) {
            float v = s_score[t * FF + f];
            if (v > best) { best = v; bi = t; }
        }
        s_idxf[f] = bi;
    } else if (tid < 128) {
        int t = tid - 64;
        float best = s_score[t * FF]; int bi = 0;
        for (int f = 1; f < FF; f++) {
            float v = s_score[t * FF + f];
            if (v > best) { best = v; bi = f; }
        }
        s_idxt[t] = bi;
    }
    __syncthreads();

    // Selected index sets (multiset -> set; max only needs membership)
    if (tid < 64) { s_usel[s_idxt[tid]] = 1; s_ssel[s_idxf[tid]] = 1; }
    __syncthreads();

    // q extremes over selected s; h extremes per t over selected u
    if (tid == 0) {
        float qmax = -1e30f, qmin = 1e30f;
        for (int s = 0; s < TT; s++)
            if (s_ssel[s]) { float q = ws[s]; qmax = fmaxf(qmax, q); qmin = fminf(qmin, q); }
        s_q[0] = qmax; s_q[1] = qmin;
    }
    if (tid < 64) {
        int t = tid;
        const float* hr = g_h + (b * TT + t) * UU;
        float hmax = -1e30f, hmin = 1e30f;
        for (int u = 0; u < UU; u++)
            if (s_usel[u]) { float h = hr[u]; hmax = fmaxf(hmax, h); hmin = fminf(hmin, h); }
        s_hmax[t] = hmax; s_hmin[t] = hmin;
    }
    __syncthreads();

    // flat[t*F+f] = tanh( extremal h*q*x )  (max of tanh = tanh of max arg)
    {
        float qmax = s_q[0], qmin = s_q[1];
        for (int i = tid; i < TF; i += 256) {
            int t = i >> 6;
            float x  = g_out[b * TF + i];
            float hM = s_hmax[t], hm = s_hmin[t];
            float p1 = hM * qmax, p2 = hM * qmin, p3 = hm * qmax, p4 = hm * qmin;
            float pqmax = fmaxf(fmaxf(p1, p2), fmaxf(p3, p4));
            float pqmin = fminf(fminf(p1, p2), fminf(p3, p4));
            float arg = (x >= 0.f) ? x * pqmax : x * pqmin;
            s_flat[i] = tanhf(arg);
        }
    }
    __syncthreads();

    // logits[m] = flat . mem_keys[m,:]   (warp w handles 8 m's)
    {
        int wid = tid >> 5, lane = tid & 31;
        for (int mi = 0; mi < 8; mi++) {
            int m = wid * 8 + mi;
            const float* kr = mem_keys + m * TF;
            float acc = 0.f;
#pragma unroll 4
            for (int j = lane; j < TF; j += 32)
                acc = fmaf(s_flat[j], kr[j], acc);
            for (int o = 16; o; o >>= 1)
                acc += __shfl_xor_sync(0xffffffffu, acc, o);
            if (lane == 0) s_logit[m] = acc;
        }
    }
    __syncthreads();

    // softmax (max-subtracted, matching jax.nn.softmax)
    if (tid == 0) {
        float ml = s_logit[0];
        for (int m = 1; m < MM; m++) ml = fmaxf(ml, s_logit[m]);
        s_red[0] = ml;
    }
    __syncthreads();
    if (tid < MM) s_attn[tid] = expf(s_logit[tid] - s_red[0]);
    __syncthreads();
    if (tid == 0) {
        float sum = 0.f, mx = 0.f;
        for (int m = 0; m < MM; m++) { sum += s_attn[m]; mx = fmaxf(mx, s_attn[m]); }
        s_red[1] = 1.f / sum;
        s_red[2] = mx / sum;   // importance = max(attn)
    }
    __syncthreads();

    // targets[f] = attn @ mem_vals
    if (tid < FF) {
        int f = tid;
        float acc = 0.f;
        for (int m = 0; m < MM; m++)
            acc = fmaf(s_attn[m], mem_vals[m * FF + f], acc);
        s_tgt[f] = acc * s_red[1];
    }
    __syncthreads();

    // dist[t] = 0.5 - hard_sigmoid(||inputs[b,t,:] - targets||); imp tiled over t
    if (tid < TT) {
        int t = tid;
        const float* ir = inputs + (b * TT + t) * FF;
        float acc = 0.f;
        for (int f = 0; f < FF; f++) {
            float d = ir[f] - s_tgt[f];
            acc = fmaf(d, d, acc);
        }
        float nrm = sqrtf(acc);
        float hs  = fminf(fmaxf(0.2f * nrm + 0.5f, 0.f), 1.f);
        d_dist[b * TT + t] = 0.5f - hs;
        d_imp [b * TT + t] = s_red[2];
    }
}

// ---------------------------------------------------------------------------
// Output layout (return order, flattened & concatenated):
//   dist [B*T] | importances [B*T] | output [B*T*F]
// ---------------------------------------------------------------------------
extern "C" void kernel_launch(void* const* d_in, const int* in_sizes, int n_in,
                              void* d_out, int out_size)
{
    const float* inputs   = (const float*)d_in[0];
    const float* Wk       = (const float*)d_in[1];
    const float* bk       = (const float*)d_in[2];
    const float* Wv       = (const float*)d_in[3];
    const float* bv       = (const float*)d_in[4];
    const float* ws       = (const float*)d_in[5];
    const float* mem_keys = (const float*)d_in[6];
    const float* mem_vals = (const float*)d_in[7];

    float* out       = (float*)d_out;
    float* d_dist    = out;                 // B*T
    float* d_imp     = out + BB * TT;       // B*T
    float* out_final = out + 2 * BB * TT;   // B*T*F

    kA<<<BB * TT, 64>>>(inputs, Wk, bk, Wv, bv, ws, out_final);
    kB<<<BB, 256>>>(inputs, ws, mem_keys, mem_vals, d_dist, d_imp);
}

// round 3
// speedup vs baseline: 2.3359x; 2.3359x over previous
#include <cuda_runtime.h>
#include <math.h>

#define BB 4
#define TT 64
#define FF 64
#define UU 64
#define MM 64
#define TF 4096   // T*F

// Scratch (device globals: no allocation allowed)
__device__ float g_h[BB * TT * UU];
__device__ float g_out[BB * TT * FF];
__device__ float g_score[BB * TT * FF];
__device__ float g_flat[BB * TF];
__device__ float g_logit[BB * MM];

// ---------------------------------------------------------------------------
// K_A: one block per (b,t), 64 threads.
//   h[u]     = tanh(inputs[b,t,:] @ Wk[:,u] + bk[u])
//   out[f]   = h @ Wv[:,f] + bv[f]            (also final "output" tensor)
//   score[f] = sum_u tanh(h[u] * out[f] * w_s[63])
// ---------------------------------------------------------------------------
__global__ void __launch_bounds__(64) kA(
    const float* __restrict__ inputs, const float* __restrict__ Wk,
    const float* __restrict__ bk,     const float* __restrict__ Wv,
    const float* __restrict__ bv,     const float* __restrict__ ws,
    float* __restrict__ out_final)
{
    int bt  = blockIdx.x;      // b*64 + t
    int tid = threadIdx.x;     // 0..63

    __shared__ float s_in[FF];
    __shared__ float s_h[UU];

    s_in[tid] = inputs[bt * FF + tid];
    __syncthreads();

    // h[u], u = tid
    float acc = bk[tid];
#pragma unroll 16
    for (int f = 0; f < FF; f++)
        acc = fmaf(s_in[f], Wk[f * UU + tid], acc);
    float hv = tanhf(acc);
    s_h[tid] = hv;
    g_h[bt * UU + tid] = hv;
    __syncthreads();

    // out[f], f = tid
    float acc2 = bv[tid];
#pragma unroll 16
    for (int u = 0; u < UU; u++)
        acc2 = fmaf(s_h[u], Wv[u * FF + tid], acc2);
    g_out[bt * FF + tid]     = acc2;
    out_final[bt * FF + tid] = acc2;

    // score[f]
    float c  = acc2 * ws[63];
    float sc = 0.f;
#pragma unroll 8
    for (int u = 0; u < UU; u++)
        sc += tanhf(s_h[u] * c);
    g_score[bt * FF + tid] = sc;
}

// ---------------------------------------------------------------------------
// K_B1: one block per batch, 256 threads. Argmax paths, set extremes,
// flat = tanh(extreme arg) -> g_flat.
// ---------------------------------------------------------------------------
__global__ void __launch_bounds__(256) kB1(
    const float* __restrict__ ws)
{
    int b   = blockIdx.x;
    int tid = threadIdx.x;

    __shared__ float s_score[TF];           // 16 KB
    __shared__ int   s_idxt[TT], s_idxf[FF];
    __shared__ int   s_usel[UU], s_ssel[TT];
    __shared__ float s_hmax[TT], s_hmin[TT];
    __shared__ float s_q[2];                // qmax, qmin

    // Load this batch's score matrix
    {
        const float4* gs4 = (const float4*)(g_score + b * TF);
        float4* ss4 = (float4*)s_score;
        for (int i = tid; i < TF / 4; i += 256) ss4[i] = gs4[i];
    }
    if (tid < 64) { s_usel[tid] = 0; s_ssel[tid] = 0; }
    __syncthreads();

    // idx_f[f] = argmax_t score[t,f] (first max); idx_t[t] = argmax_f score[t,f]
    if (tid < 64) {
        int f = tid;
        float best = s_score[f]; int bi = 0;
        for (int t = 1; t < TT; t++) {
            float v = s_score[t * FF + f];
            if (v > best) { best = v; bi = t; }
        }
        s_idxf[f] = bi;
    } else if (tid < 128) {
        int t = tid - 64;
        float best = s_score[t * FF]; int bi = 0;
        for (int f = 1; f < FF; f++) {
            float v = s_score[t * FF + f];
            if (v > best) { best = v; bi = f; }
        }
        s_idxt[t] = bi;
    }
    __syncthreads();

    // Selected index sets (multiset -> set; max only needs membership)
    if (tid < 64) { s_usel[s_idxt[tid]] = 1; s_ssel[s_idxf[tid]] = 1; }
    __syncthreads();

    // q extremes over selected s; h extremes per t over selected u
    if (tid == 0) {
        float qmax = -1e30f, qmin = 1e30f;
        for (int s = 0; s < TT; s++)
            if (s_ssel[s]) { float q = ws[s]; qmax = fmaxf(qmax, q); qmin = fminf(qmin, q); }
        s_q[0] = qmax; s_q[1] = qmin;
    }
    if (tid < 64) {
        int t = tid;
        const float* hr = g_h + (b * TT + t) * UU;
        float hmax = -1e30f, hmin = 1e30f;
        for (int u = 0; u < UU; u++)
            if (s_usel[u]) { float h = hr[u]; hmax = fmaxf(hmax, h); hmin = fminf(hmin, h); }
        s_hmax[t] = hmax; s_hmin[t] = hmin;
    }
    __syncthreads();

    // flat[t*F+f] = tanh( extremal h*q*x )  (max of tanh = tanh of max arg)
    {
        float qmax = s_q[0], qmin = s_q[1];
        for (int i = tid; i < TF; i += 256) {
            int t = i >> 6;
            float x  = g_out[b * TF + i];
            float hM = s_hmax[t], hm = s_hmin[t];
            float p1 = hM * qmax, p2 = hM * qmin, p3 = hm * qmax, p4 = hm * qmin;
            float pqmax = fmaxf(fmaxf(p1, p2), fmaxf(p3, p4));
            float pqmin = fminf(fminf(p1, p2), fminf(p3, p4));
            float arg = (x >= 0.f) ? x * pqmax : x * pqmin;
            g_flat[b * TF + i] = tanhf(arg);
        }
    }
}

// ---------------------------------------------------------------------------
// K_B2: one block per (b, m): logits[b,m] = flat[b,:] . mem_keys[m,:]
// 128 threads, float4 loads, MLP ~8 per thread.
// ---------------------------------------------------------------------------
__global__ void __launch_bounds__(128) kB2(
    const float* __restrict__ mem_keys)
{
    int m   = blockIdx.x;     // 0..63
    int b   = blockIdx.y;     // 0..3
    int tid = threadIdx.x;    // 0..127

    const float4* fl = (const float4*)(g_flat + b * TF);
    const float4* kr = (const float4*)(mem_keys + m * TF);

    float acc = 0.f;
#pragma unroll
    for (int j = 0; j < 8; j++) {
        int i = tid + j * 128;        // 1024 float4 total
        float4 a = fl[i];
        float4 k = __ldg(&kr[i]);
        acc = fmaf(a.x, k.x, acc);
        acc = fmaf(a.y, k.y, acc);
        acc = fmaf(a.z, k.z, acc);
        acc = fmaf(a.w, k.w, acc);
    }
    // warp reduce
    for (int o = 16; o; o >>= 1)
        acc += __shfl_xor_sync(0xffffffffu, acc, o);

    __shared__ float s_part[4];
    int wid = tid >> 5, lane = tid & 31;
    if (lane == 0) s_part[wid] = acc;
    __syncthreads();
    if (tid == 0)
        g_logit[b * MM + m] = s_part[0] + s_part[1] + s_part[2] + s_part[3];
}

// ---------------------------------------------------------------------------
// K_B3: one block per batch, 128 threads: softmax, targets, importance, dist.
// ---------------------------------------------------------------------------
__global__ void __launch_bounds__(128) kB3(
    const float* __restrict__ inputs, const float* __restrict__ mem_vals,
    float* __restrict__ d_dist, float* __restrict__ d_imp)
{
    int b   = blockIdx.x;
    int tid = threadIdx.x;

    __shared__ float s_attn[MM];
    __shared__ float s_tgt[FF];
    __shared__ float s_red[2];   // invsum, importance

    // softmax over 64 logits: warp 0 (lanes 0,1 handle 2 each? use 64 threads)
    if (tid < MM) {
        float v = g_logit[b * MM + tid];
        // block max via two warps + shfl within 64 threads: do via shared
        s_attn[tid] = v;
    }
    __syncthreads();
    if (tid == 0) {
        float ml = s_attn[0];
        for (int m = 1; m < MM; m++) ml = fmaxf(ml, s_attn[m]);
        s_red[0] = ml;
    }
    __syncthreads();
    if (tid < MM) s_attn[tid] = expf(s_attn[tid] - s_red[0]);
    __syncthreads();
    if (tid == 0) {
        float sum = 0.f, mx = 0.f;
        for (int m = 0; m < MM; m++) { sum += s_attn[m]; mx = fmaxf(mx, s_attn[m]); }
        s_red[0] = 1.f / sum;
        s_red[1] = mx / sum;   // importance = max(attn)
    }
    __syncthreads();

    // targets[f] = attn @ mem_vals
    if (tid < FF) {
        int f = tid;
        float acc = 0.f;
#pragma unroll 8
        for (int m = 0; m < MM; m++)
            acc = fmaf(s_attn[m], mem_vals[m * FF + f], acc);
        s_tgt[f] = acc * s_red[0];
    }
    __syncthreads();

    // dist[t] = 0.5 - hard_sigmoid(||inputs[b,t,:] - targets||); imp tiled
    if (tid < TT) {
        int t = tid;
        const float* ir = inputs + (b * TT + t) * FF;
        float acc = 0.f;
#pragma unroll 8
        for (int f = 0; f < FF; f++) {
            float d = ir[f] - s_tgt[f];
            acc = fmaf(d, d, acc);
        }
        float nrm = sqrtf(acc);
        float hs  = fminf(fmaxf(0.2f * nrm + 0.5f, 0.f), 1.f);
        d_dist[b * TT + t] = 0.5f - hs;
        d_imp [b * TT + t] = s_red[1];
    }
}

// ---------------------------------------------------------------------------
// Output layout: dist [B*T] | importances [B*T] | output [B*T*F]
// ---------------------------------------------------------------------------
extern "C" void kernel_launch(void* const* d_in, const int* in_sizes, int n_in,
                              void* d_out, int out_size)
{
    const float* inputs   = (const float*)d_in[0];
    const float* Wk       = (const float*)d_in[1];
    const float* bk       = (const float*)d_in[2];
    const float* Wv       = (const float*)d_in[3];
    const float* bv       = (const float*)d_in[4];
    const float* ws       = (const float*)d_in[5];
    const float* mem_keys = (const float*)d_in[6];
    const float* mem_vals = (const float*)d_in[7];

    float* out       = (float*)d_out;
    float* d_dist    = out;                 // B*T
    float* d_imp     = out + BB * TT;       // B*T
    float* out_final = out + 2 * BB * TT;   // B*T*F

    kA<<<BB * TT, 64>>>(inputs, Wk, bk, Wv, bv, ws, out_final);
    kB1<<<BB, 256>>>(ws);
    dim3 g2(MM, BB);
    kB2<<<g2, 128>>>(mem_keys);
    kB3<<<BB, 128>>>(inputs, mem_vals, d_dist, d_imp);
}